// round 6
// baseline (speedup 1.0000x reference)
#include <cuda_runtime.h>
#include <cstdint>

// Tensor-train chain, fp32 f32x2, r-pair packing, single barrier/step,
// warp-private v handoff, distributed finalize, 147 CTAs x 28 batches.
//
// Step s: t[i][r] = sum_l v[l]*C_s[l][i][r]; v'[r] = sum_i x[b][s+1][i]*t[i][r]
// 512 threads = 4 l-quarters (q) x 4 batch-groups (bg, 7 batches each).
// Thread: 7 batches x f32x2{r0,r0+1}, r0 = 2*lane.

#define BATCH   4096
#define LEN     128
#define RANK    64
#define NSTEP   126
#define CSTEP   16384          // floats per mid-core step (256*64)
#define TB      28             // batches per CTA
#define NB      7              // batches per bg
#define GRID    147            // 147*28 = 4116 >= 4096 (padded)
#define THREADS 512

// smem layout (bytes):
//   Cbuf : 2*CSTEP floats                = 131072
//   vbuf : [64 rows][32 cols] float2     =  16384   (col = bg*8 + m, m<7)
//   scr  : [2 par][16 warp][7 m][33] f2  =  59136   (33 = 32 lanes + 1 pad)
#define VCOLS 32
#define SSTR  33
#define SMEM_BYTES (2*CSTEP*4 + 64*VCOLS*8 + 2*16*NB*SSTR*8)

extern __shared__ float smem_f[];

__device__ __forceinline__ uint64_t fma2(uint64_t a, uint64_t b, uint64_t c) {
    uint64_t d;
    asm("fma.rn.f32x2 %0, %1, %2, %3;" : "=l"(d) : "l"(a), "l"(b), "l"(c));
    return d;
}
__device__ __forceinline__ uint64_t mul2(uint64_t a, uint64_t b) {
    uint64_t d;
    asm("mul.rn.f32x2 %0, %1, %2;" : "=l"(d) : "l"(a), "l"(b));
    return d;
}
__device__ __forceinline__ uint64_t dup2(float f) {
    uint64_t d;
    asm("mov.b64 %0, {%1, %1};" : "=l"(d) : "f"(f));
    return d;
}
__device__ __forceinline__ float2 u2f(uint64_t a) {
    return *reinterpret_cast<float2*>(&a);
}
__device__ __forceinline__ uint32_t smem_u32(const void* p) {
    return (uint32_t)__cvta_generic_to_shared(p);
}
__device__ __forceinline__ void cp_async16(uint32_t dst, const void* src) {
    asm volatile("cp.async.cg.shared.global [%0], [%1], 16;\n" :: "r"(dst), "l"(src));
}

__global__ void __launch_bounds__(THREADS, 1)
tt_chain_kernel(const float* __restrict__ x,    // [B, 128, 4]
                const float* __restrict__ fc,   // [4, 64]
                const float* __restrict__ mc,   // [126, 64, 4, 64]
                const float* __restrict__ lc,   // [64, 4]
                float* __restrict__ out)        // [B, 1]
{
    float*  Cbuf = smem_f;
    float2* vbuf = (float2*)(smem_f + 2*CSTEP);        // [64][VCOLS]
    float2* scr  = vbuf + 64*VCOLS;                    // [2][16][7][SSTR]
    float*  epi  = (float*)scr;                        // aliases scr par 0

    const int tid  = threadIdx.x;
    const int warp = tid >> 5;
    const int lane = tid & 31;
    const int q    = warp >> 2;            // l-quarter: [16q, 16q+16)
    const int bg   = warp & 3;
    const int lbase = q * 16;
    const int gb0  = blockIdx.x * TB + bg * NB;

    // clamped per-batch x offsets (floats)
    int xo[NB];
    #pragma unroll
    for (int m = 0; m < NB; ++m) {
        int b = gb0 + m;
        if (b > BATCH - 1) b = BATCH - 1;
        xo[m] = b * (LEN * 4);
    }

    // ---- prefetch C[0] ----
    {
        uint32_t dst = smem_u32(Cbuf);
        #pragma unroll
        for (int j = 0; j < 8; ++j) {
            int idx = j * THREADS + tid;
            cp_async16(dst + idx * 16, mc + idx * 4);
        }
        asm volatile("cp.async.commit_group;\n");
    }

    // ---- v0: each warp fills its own vbuf slice (rows in its quarter) ----
    #pragma unroll
    for (int cc = 0; cc < 2; ++cc) {
        int c  = cc * 32 + lane;       // combo 0..63
        int rp = c >> 3;               // 0..7
        int m  = c & 7;                // 0..7 (7 = pad, skip)
        if (m < NB) {
            int r0v = lbase + 2 * rp;
            float4 x0 = *(const float4*)(x + xo[m]);
            float vlo = fc[r0v]       * x0.x + fc[64 + r0v]       * x0.y
                      + fc[128 + r0v] * x0.z + fc[192 + r0v]      * x0.w;
            float vhi = fc[r0v + 1]     * x0.x + fc[64 + r0v + 1]  * x0.y
                      + fc[128 + r0v + 1] * x0.z + fc[192 + r0v + 1] * x0.w;
            vbuf[r0v * VCOLS + bg * 8 + m]       = make_float2(vlo, vlo);
            vbuf[(r0v + 1) * VCOLS + bg * 8 + m] = make_float2(vhi, vhi);
        }
    }
    asm volatile("cp.async.wait_group 0;\n");   // C[0] landed (own copies)

    // ---- main sequential chain: ONE __syncthreads per step ----
    #pragma unroll 1
    for (int s = 0; s < NSTEP; ++s) {
        __syncthreads();   // C[s] visible to all; scr[(s-1)&1] complete; buf[(s+1)&1] free

        // prefetch C[s+1] (issued AFTER barrier so buffer reuse is safe)
        if (s + 1 < NSTEP) {
            uint32_t dst = smem_u32(Cbuf + ((s + 1) & 1) * CSTEP);
            const float* src = mc + (size_t)(s + 1) * CSTEP;
            #pragma unroll
            for (int j = 0; j < 8; ++j) {
                int idx = j * THREADS + tid;
                cp_async16(dst + idx * 16, src + idx * 4);
            }
            asm volatile("cp.async.commit_group;\n");
        }

        // finalize v_s from scratch partials (warp-private vbuf slice)
        if (s > 0) {
            const float2* sbase = scr + (size_t)((s - 1) & 1) * (16 * NB * SSTR);
            #pragma unroll
            for (int cc = 0; cc < 2; ++cc) {
                int c  = cc * 32 + lane;
                int rp = c >> 3;
                int m  = c & 7;
                if (m < NB) {
                    int li = 8 * q + rp;
                    const float2* sp = sbase + (size_t)(bg * NB + m) * SSTR + li;
                    // q' stride = 4 warps * NB * SSTR
                    float2 p0 = sp[0];
                    float2 p1 = sp[4 * NB * SSTR];
                    float2 p2 = sp[8 * NB * SSTR];
                    float2 p3 = sp[12 * NB * SSTR];
                    float vx = (p0.x + p1.x) + (p2.x + p3.x);
                    float vy = (p0.y + p1.y) + (p2.y + p3.y);
                    int r0v = lbase + 2 * rp;
                    vbuf[r0v * VCOLS + bg * 8 + m]       = make_float2(vx, vx);
                    vbuf[(r0v + 1) * VCOLS + bg * 8 + m] = make_float2(vy, vy);
                }
            }
        }
        __syncwarp();   // vbuf slice ready for this warp's own k-loop reads

        // ---- k-loop: t[i][m]{r0,r1} += vdup[m] * C[l,i,{r0,r1}] ----
        const float* Cs = Cbuf + (s & 1) * CSTEP + 2 * lane;
        uint64_t t[4][NB];
        #pragma unroll
        for (int i = 0; i < 4; ++i)
            #pragma unroll
            for (int m = 0; m < NB; ++m) t[i][m] = 0ull;

        #pragma unroll 4
        for (int ll = 0; ll < 16; ++ll) {
            int l = lbase + ll;
            const float2* vr = vbuf + l * VCOLS + bg * 8;
            ulonglong2 u0 = *(const ulonglong2*)(vr);       // m0,m1
            ulonglong2 u1 = *(const ulonglong2*)(vr + 2);   // m2,m3
            ulonglong2 u2 = *(const ulonglong2*)(vr + 4);   // m4,m5
            uint64_t   v6 = *(const uint64_t*)(vr + 6);     // m6
            uint64_t vd[NB] = { u0.x, u0.y, u1.x, u1.y, u2.x, u2.y, v6 };
            #pragma unroll
            for (int i = 0; i < 4; ++i) {
                uint64_t c2v = *(const uint64_t*)(Cs + (4 * l + i) * RANK);
                #pragma unroll
                for (int m = 0; m < NB; ++m)
                    t[i][m] = fma2(vd[m], c2v, t[i][m]);
            }
        }

        // ---- combine with x[., s+1, .] ----
        uint64_t vn[NB];
        #pragma unroll
        for (int m = 0; m < NB; ++m) {
            float4 xs = *(const float4*)(x + xo[m] + (s + 1) * 4);
            uint64_t v = mul2(dup2(xs.x), t[0][m]);
            v = fma2(dup2(xs.y), t[1][m], v);
            v = fma2(dup2(xs.z), t[2][m], v);
            v = fma2(dup2(xs.w), t[3][m], v);
            vn[m] = v;
        }

        // ---- write partials to scratch (parity s&1) ----
        {
            float2* sw = scr + (size_t)(s & 1) * (16 * NB * SSTR)
                             + (size_t)(warp * NB) * SSTR + lane;
            #pragma unroll
            for (int m = 0; m < NB; ++m)
                sw[m * SSTR] = u2f(vn[m]);
        }

        asm volatile("cp.async.wait_group 0;\n");   // C[s+1] landed (own copies)
    }

    // ---- epilogue: finalize v_126, dot with last_core vector, reduce ----
    __syncthreads();    // scr[1] (s=125 partials) complete
    {
        const float2* sbase = scr + (size_t)((NSTEP - 1) & 1) * (16 * NB * SSTR);
        #pragma unroll
        for (int cc = 0; cc < 2; ++cc) {
            int c  = cc * 32 + lane;
            int rp = c >> 3;
            int m  = c & 7;
            if (m < NB) {
                int li = 8 * q + rp;
                const float2* sp = sbase + (size_t)(bg * NB + m) * SSTR + li;
                float2 p0 = sp[0];
                float2 p1 = sp[4 * NB * SSTR];
                float2 p2 = sp[8 * NB * SSTR];
                float2 p3 = sp[12 * NB * SSTR];
                float vx = (p0.x + p1.x) + (p2.x + p3.x);
                float vy = (p0.y + p1.y) + (p2.y + p3.y);
                int r0v = lbase + 2 * rp;
                float4 xe = *(const float4*)(x + xo[m] + 127 * 4);
                float4 l0 = *(const float4*)(lc + r0v * 4);
                float4 l1 = *(const float4*)(lc + (r0v + 1) * 4);
                float lv0 = l0.x*xe.x + l0.y*xe.y + l0.z*xe.z + l0.w*xe.w;
                float lv1 = l1.x*xe.x + l1.y*xe.y + l1.z*xe.z + l1.w*xe.w;
                epi[(bg * NB + m) * 33 + li] = vx * lv0 + vy * lv1;
            }
        }
    }
    __syncthreads();
    if (tid < TB) {
        int b = blockIdx.x * TB + tid;
        if (b < BATCH) {
            float sum = 0.f;
            #pragma unroll
            for (int k = 0; k < 32; ++k) sum += epi[tid * 33 + k];
            out[b] = sum;
        }
    }
}

extern "C" void kernel_launch(void* const* d_in, const int* in_sizes, int n_in,
                              void* d_out, int out_size) {
    const float* x  = (const float*)d_in[0];   // input_data [4096,128,4]
    const float* fc = (const float*)d_in[1];   // first_core [4,64]
    const float* mc = (const float*)d_in[2];   // mid_cores  [126,64,4,64]
    const float* lc = (const float*)d_in[3];   // last_core  [64,4]
    float* out = (float*)d_out;

    cudaFuncSetAttribute(tt_chain_kernel,
                         cudaFuncAttributeMaxDynamicSharedMemorySize, SMEM_BYTES);

    tt_chain_kernel<<<GRID, THREADS, SMEM_BYTES>>>(x, fc, mc, lc, out);
}

// round 7
// speedup vs baseline: 1.0450x; 1.0450x over previous
#include <cuda_runtime.h>
#include <cstdint>

// Tensor-train chain, fp32 f32x2. v lives in REGISTERS across steps
// (thread finalizes exactly the slots it consumes); intra-warp v
// distribution via shfl; C is the only large crossbar stream.
//
// 512 thr = 4 l-quarters (q = warp>>2) x 4 batch-groups (bg = warp&3 -> SMSP).
// Thread: r-pair {2*lane, 2*lane+1}, accumulates all 4 batch-pairs of bg.
// v slots per thread: pair P = lane>>3, l = 16q + 2*(lane&7) {+1}.

#define BATCH   4096
#define LEN     128
#define RANK    64
#define NSTEP   126
#define CSTEP   16384          // floats per mid-core step
#define TB      32
#define GRID    128
#define THREADS 512

// smem: Cbuf 2*CSTEP floats | scr 2par*4q*4bg*4p*32lane ulonglong2 | epi 64 f2
#define SCR_N   (2*4*4*4*32)   // 4096 ulonglong2
#define SMEM_BYTES (2*CSTEP*4 + SCR_N*16 + 64*8)

extern __shared__ float smem_f[];

__device__ __forceinline__ uint64_t fma2(uint64_t a, uint64_t b, uint64_t c) {
    uint64_t d;
    asm("fma.rn.f32x2 %0, %1, %2, %3;" : "=l"(d) : "l"(a), "l"(b), "l"(c));
    return d;
}
__device__ __forceinline__ uint64_t mul2(uint64_t a, uint64_t b) {
    uint64_t d;
    asm("mul.rn.f32x2 %0, %1, %2;" : "=l"(d) : "l"(a), "l"(b));
    return d;
}
__device__ __forceinline__ uint64_t add2(uint64_t a, uint64_t b) {
    uint64_t d;
    asm("add.rn.f32x2 %0, %1, %2;" : "=l"(d) : "l"(a), "l"(b));
    return d;
}
__device__ __forceinline__ uint64_t dup2(float f) {
    uint64_t d;
    asm("mov.b64 %0, {%1, %1};" : "=l"(d) : "f"(f));
    return d;
}
__device__ __forceinline__ uint64_t pack2(float a, float b) {
    uint64_t d;
    asm("mov.b64 %0, {%1, %2};" : "=l"(d) : "f"(a), "f"(b));
    return d;
}
__device__ __forceinline__ float2 u2f(uint64_t a) {
    return *reinterpret_cast<float2*>(&a);
}
__device__ __forceinline__ uint64_t shfl64(uint64_t v, int src) {
    uint32_t lo = (uint32_t)v, hi = (uint32_t)(v >> 32);
    lo = __shfl_sync(0xffffffffu, lo, src);
    hi = __shfl_sync(0xffffffffu, hi, src);
    return ((uint64_t)hi << 32) | lo;
}
__device__ __forceinline__ uint32_t smem_u32(const void* p) {
    return (uint32_t)__cvta_generic_to_shared(p);
}
__device__ __forceinline__ void cp_async16(uint32_t dst, const void* src) {
    asm volatile("cp.async.cg.shared.global [%0], [%1], 16;\n" :: "r"(dst), "l"(src));
}

__global__ void __launch_bounds__(THREADS, 1)
tt_chain_kernel(const float* __restrict__ x,    // [B, 128, 4]
                const float* __restrict__ fc,   // [4, 64]
                const float* __restrict__ mc,   // [126, 64, 4, 64]
                const float* __restrict__ lc,   // [64, 4]
                float* __restrict__ out)        // [B, 1]
{
    float*      Cbuf = smem_f;
    ulonglong2* scr  = (ulonglong2*)(smem_f + 2*CSTEP);  // [2][4q'][4bg][4p][32]
    float2*     epi  = (float2*)(scr + SCR_N);           // [4q][4bg][4p]

    const int tid  = threadIdx.x;
    const int warp = tid >> 5;
    const int lane = tid & 31;
    const int q    = warp >> 2;            // l-quarter [16q, 16q+16)
    const int bg   = warp & 3;             // -> SMSP
    const int P    = lane >> 3;            // pair within bg
    const int m    = lane & 7;
    const int gbase = blockIdx.x * TB + bg * 8;
    const int b0s = (gbase + 2*P) * (LEN*4);   // x offsets for this thread's slot pair
    const int b1s = b0s + LEN*4;

    // ---- prefetch C[0] ----
    {
        uint32_t dst = smem_u32(Cbuf);
        #pragma unroll
        for (int j = 0; j < 8; ++j) {
            int idx = j * THREADS + tid;
            cp_async16(dst + idx * 16, mc + idx * 4);
        }
        asm volatile("cp.async.commit_group;\n");
    }

    // ---- prologue: v0,v1 in registers ----
    // v0 = {v[b0][l0], v[b1][l0]}, v1 = same for l0+1, l0 = 16q + 2m
    uint64_t v0, v1;
    {
        const int l0 = 16*q + 2*m;
        float4 xa = *(const float4*)(x + b0s);
        float4 xb = *(const float4*)(x + b1s);
        float f00 = fc[l0],     f01 = fc[64+l0],   f02 = fc[128+l0],   f03 = fc[192+l0];
        float f10 = fc[l0+1],   f11 = fc[64+l0+1], f12 = fc[128+l0+1], f13 = fc[192+l0+1];
        float a0 = f00*xa.x + f01*xa.y + f02*xa.z + f03*xa.w;
        float b0v = f00*xb.x + f01*xb.y + f02*xb.z + f03*xb.w;
        float a1 = f10*xa.x + f11*xa.y + f12*xa.z + f13*xa.w;
        float b1v = f10*xb.x + f11*xb.y + f12*xb.z + f13*xb.w;
        v0 = pack2(a0, b0v);
        v1 = pack2(a1, b1v);
    }
    asm volatile("cp.async.wait_group 0;\n");   // own C[0] chunks landed

    // ---- main chain: ONE __syncthreads per step ----
    #pragma unroll 1
    for (int s = 0; s < NSTEP; ++s) {
        __syncthreads();   // C[s] + scr[(s-1)&1] visible; Cbuf[(s+1)&1] free

        if (s + 1 < NSTEP) {
            uint32_t dst = smem_u32(Cbuf + ((s + 1) & 1) * CSTEP);
            const float* src = mc + (size_t)(s + 1) * CSTEP;
            #pragma unroll
            for (int j = 0; j < 8; ++j) {
                int idx = j * THREADS + tid;
                cp_async16(dst + idx * 16, src + idx * 4);
            }
            asm volatile("cp.async.commit_group;\n");
        }

        // finalize v_s into registers (sum 4 q' partials), except s==0
        if (s > 0) {
            const int par = (s - 1) & 1;
            const int ridx = ((par*4)*4 + bg)*4 + P;       // q'=0 base
            const int roff = 8*q + m;
            ulonglong2 a = scr[(ridx      )*32 + roff];
            ulonglong2 b = scr[(ridx + 16 )*32 + roff];    // q'=1: +4*4
            ulonglong2 c = scr[(ridx + 32 )*32 + roff];
            ulonglong2 d = scr[(ridx + 48 )*32 + roff];
            v0 = add2(add2(a.x, b.x), add2(c.x, d.x));
            v1 = add2(add2(a.y, b.y), add2(c.y, d.y));
        }

        // prefetch x[., s+1, .] for all 4 pairs of bg (combine stage)
        float4 xa[4], xb[4];
        #pragma unroll
        for (int p = 0; p < 4; ++p) {
            const float* xp = x + (gbase + 2*p) * (LEN*4) + (s + 1) * 4;
            xa[p] = *(const float4*)xp;
            xb[p] = *(const float4*)(xp + LEN*4);
        }

        // ---- k-loop over the warp's 16 l values ----
        const float2* Cs = (const float2*)(Cbuf + (s & 1) * CSTEP) + lane;
        uint64_t t[4][4][2];
        #pragma unroll
        for (int i = 0; i < 4; ++i)
            #pragma unroll
            for (int p = 0; p < 4; ++p) { t[i][p][0] = 0ull; t[i][p][1] = 0ull; }

        #pragma unroll
        for (int ll = 0; ll < 16; ++ll) {
            const int l = 16*q + ll;
            const int sl = ll >> 1;
            uint64_t vsrc = (ll & 1) ? v1 : v0;
            uint64_t vd0 = shfl64(vsrc, sl);
            uint64_t vd1 = shfl64(vsrc, 8 + sl);
            uint64_t vd2 = shfl64(vsrc, 16 + sl);
            uint64_t vd3 = shfl64(vsrc, 24 + sl);
            #pragma unroll
            for (int i = 0; i < 4; ++i) {
                float2 c = Cs[(4*l + i) * 32];     // {C[l,i,2lane], C[l,i,2lane+1]}
                uint64_t ca = dup2(c.x), cb = dup2(c.y);
                t[i][0][0] = fma2(vd0, ca, t[i][0][0]);
                t[i][0][1] = fma2(vd0, cb, t[i][0][1]);
                t[i][1][0] = fma2(vd1, ca, t[i][1][0]);
                t[i][1][1] = fma2(vd1, cb, t[i][1][1]);
                t[i][2][0] = fma2(vd2, ca, t[i][2][0]);
                t[i][2][1] = fma2(vd2, cb, t[i][2][1]);
                t[i][3][0] = fma2(vd3, ca, t[i][3][0]);
                t[i][3][1] = fma2(vd3, cb, t[i][3][1]);
            }
        }

        // ---- combine with x and write q-partials ----
        {
            const int widx = (((s & 1)*4 + q)*4 + bg)*4;
            #pragma unroll
            for (int p = 0; p < 4; ++p) {
                uint64_t xp0 = pack2(xa[p].x, xb[p].x);
                uint64_t xp1 = pack2(xa[p].y, xb[p].y);
                uint64_t xp2 = pack2(xa[p].z, xb[p].z);
                uint64_t xp3 = pack2(xa[p].w, xb[p].w);
                uint64_t n0 = mul2(xp0, t[0][p][0]);
                n0 = fma2(xp1, t[1][p][0], n0);
                n0 = fma2(xp2, t[2][p][0], n0);
                n0 = fma2(xp3, t[3][p][0], n0);
                uint64_t n1 = mul2(xp0, t[0][p][1]);
                n1 = fma2(xp1, t[1][p][1], n1);
                n1 = fma2(xp2, t[2][p][1], n1);
                n1 = fma2(xp3, t[3][p][1], n1);
                ulonglong2 w; w.x = n0; w.y = n1;
                scr[(widx + p)*32 + lane] = w;
            }
        }

        asm volatile("cp.async.wait_group 0;\n");   // own C[s+1] chunks landed
    }

    // ---- epilogue ----
    __syncthreads();   // scr parity 1 (s=125) complete
    {
        const int par = (NSTEP - 1) & 1;
        const int ridx = ((par*4)*4 + bg)*4 + P;
        const int roff = 8*q + m;
        ulonglong2 a = scr[(ridx      )*32 + roff];
        ulonglong2 b = scr[(ridx + 16 )*32 + roff];
        ulonglong2 c = scr[(ridx + 32 )*32 + roff];
        ulonglong2 d = scr[(ridx + 48 )*32 + roff];
        v0 = add2(add2(a.x, b.x), add2(c.x, d.x));
        v1 = add2(add2(a.y, b.y), add2(c.y, d.y));

        const int r = 16*q + 2*m;
        float4 l0 = *(const float4*)(lc + r * 4);
        float4 l1 = *(const float4*)(lc + (r + 1) * 4);
        float4 xe0 = *(const float4*)(x + b0s + 127*4);
        float4 xe1 = *(const float4*)(x + b1s + 127*4);
        float lva0 = l0.x*xe0.x + l0.y*xe0.y + l0.z*xe0.z + l0.w*xe0.w;
        float lvb0 = l0.x*xe1.x + l0.y*xe1.y + l0.z*xe1.z + l0.w*xe1.w;
        float lva1 = l1.x*xe0.x + l1.y*xe0.y + l1.z*xe0.z + l1.w*xe0.w;
        float lvb1 = l1.x*xe1.x + l1.y*xe1.y + l1.z*xe1.z + l1.w*xe1.w;
        float2 vv0 = u2f(v0), vv1 = u2f(v1);
        float px = vv0.x * lva0 + vv1.x * lva1;
        float py = vv0.y * lvb0 + vv1.y * lvb1;
        // reduce over m within each 8-lane group
        #pragma unroll
        for (int d8 = 4; d8 > 0; d8 >>= 1) {
            px += __shfl_down_sync(0xffffffffu, px, d8, 8);
            py += __shfl_down_sync(0xffffffffu, py, d8, 8);
        }
        if (m == 0) epi[(q*4 + bg)*4 + P] = make_float2(px, py);
    }
    __syncthreads();
    if (tid < 16) {
        const int bg2 = tid >> 2, P2 = tid & 3;
        float sx = 0.f, sy = 0.f;
        #pragma unroll
        for (int qq = 0; qq < 4; ++qq) {
            float2 e = epi[(qq*4 + bg2)*4 + P2];
            sx += e.x; sy += e.y;
        }
        const int b = blockIdx.x * TB + bg2 * 8 + 2 * P2;
        out[b]     = sx;
        out[b + 1] = sy;
    }
}

extern "C" void kernel_launch(void* const* d_in, const int* in_sizes, int n_in,
                              void* d_out, int out_size) {
    const float* x  = (const float*)d_in[0];   // input_data [4096,128,4]
    const float* fc = (const float*)d_in[1];   // first_core [4,64]
    const float* mc = (const float*)d_in[2];   // mid_cores  [126,64,4,64]
    const float* lc = (const float*)d_in[3];   // last_core  [64,4]
    float* out = (float*)d_out;

    cudaFuncSetAttribute(tt_chain_kernel,
                         cudaFuncAttributeMaxDynamicSharedMemorySize, SMEM_BYTES);

    tt_chain_kernel<<<GRID, THREADS, SMEM_BYTES>>>(x, fc, mc, lc, out);
}

// round 8
// speedup vs baseline: 1.2326x; 1.1794x over previous
#include <cuda_runtime.h>
#include <cstdint>

// Tensor-train chain, fp32 f32x2, batch-pair packing, TB=28 / grid=147,
// balanced {4,4,3,3} pair split rotated across l-quarters (templated),
// single barrier per step, distributed finalize through smem scratch.

#define BATCH   4096
#define LEN     128
#define RANK    64
#define NSTEP   126
#define CSTEP   16384          // floats per mid-core step
#define TB      28             // batches per CTA (14 pairs)
#define NPAIR   14
#define GRID    147            // 147*28 = 4116 >= 4096
#define THREADS 512
#define VPITCH  66             // f32x2 per vbuf pair-row (64 + 2 pad, even)

// smem: Cbuf 2*CSTEP floats | vbuf [14][VPITCH] f32x2 | scr [2][4][14][32] ull2
#define SCR_U2  (2*4*NPAIR*32)
#define SMEM_BYTES (2*CSTEP*4 + NPAIR*VPITCH*8 + SCR_U2*16)

extern __shared__ float smem_f[];

__device__ __forceinline__ uint64_t fma2(uint64_t a, uint64_t b, uint64_t c) {
    uint64_t d;
    asm("fma.rn.f32x2 %0, %1, %2, %3;" : "=l"(d) : "l"(a), "l"(b), "l"(c));
    return d;
}
__device__ __forceinline__ uint64_t mul2(uint64_t a, uint64_t b) {
    uint64_t d;
    asm("mul.rn.f32x2 %0, %1, %2;" : "=l"(d) : "l"(a), "l"(b));
    return d;
}
__device__ __forceinline__ uint64_t dup2(float f) {
    uint64_t d;
    asm("mov.b64 %0, {%1, %1};" : "=l"(d) : "f"(f));
    return d;
}
__device__ __forceinline__ uint64_t pack2(float a, float b) {
    uint64_t d;
    asm("mov.b64 %0, {%1, %2};" : "=l"(d) : "f"(a), "f"(b));
    return d;
}
__device__ __forceinline__ float2 u2f(uint64_t a) {
    return *reinterpret_cast<float2*>(&a);
}
__device__ __forceinline__ uint32_t smem_u32(const void* p) {
    return (uint32_t)__cvta_generic_to_shared(p);
}
__device__ __forceinline__ void cp_async16(uint32_t dst, const void* src) {
    asm volatile("cp.async.cg.shared.global [%0], [%1], 16;\n" :: "r"(dst), "l"(src));
}

// One step's heavy work for a warp owning P pairs.
// CsL: float2 view of current C buffer, pre-offset by this warp's q and lane.
// vrow: vbuf + base*VPITCH + 16*q (f32x2), rows indexed [p*VPITCH + llocal].
// scrW: scratch write base (ull2) for (parity, q, base), indexed [p*32 + lane].
template<int P>
__device__ __forceinline__ void step_body(
    int s, const float2* __restrict__ CsL, const float2* __restrict__ vrow,
    const float* __restrict__ x, const int* xo0, const int* xo1,
    ulonglong2* __restrict__ scrW, int lane)
{
    uint64_t t[4][P][2];
    #pragma unroll
    for (int i = 0; i < 4; ++i)
        #pragma unroll
        for (int p = 0; p < P; ++p) { t[i][p][0] = 0ull; t[i][p][1] = 0ull; }

    #pragma unroll
    for (int h = 0; h < 8; ++h) {          // l-pairs within the quarter
        const int l2 = 2 * h;
        uint64_t vA[P], vB[P];
        #pragma unroll
        for (int p = 0; p < P; ++p) {
            ulonglong2 V = *(const ulonglong2*)(vrow + p * VPITCH + l2);
            vA[p] = V.x;                    // {v[b0][l2],   v[b1][l2]}
            vB[p] = V.y;                    // {v[b0][l2+1], v[b1][l2+1]}
        }
        #pragma unroll
        for (int li = 0; li < 2; ++li) {
            #pragma unroll
            for (int i = 0; i < 4; ++i) {
                float2 c = CsL[(4 * (l2 + li) + i) * 32];  // {C[..,2lane],C[..,2lane+1]}
                uint64_t ca = dup2(c.x), cb = dup2(c.y);
                #pragma unroll
                for (int p = 0; p < P; ++p) {
                    uint64_t vv = li ? vB[p] : vA[p];
                    t[i][p][0] = fma2(vv, ca, t[i][p][0]);
                    t[i][p][1] = fma2(vv, cb, t[i][p][1]);
                }
            }
        }
    }

    // combine with x[., s+1, .] and write q-partials
    #pragma unroll
    for (int p = 0; p < P; ++p) {
        float4 xa = *(const float4*)(x + xo0[p] + (s + 1) * 4);
        float4 xb = *(const float4*)(x + xo1[p] + (s + 1) * 4);
        uint64_t xp0 = pack2(xa.x, xb.x);
        uint64_t xp1 = pack2(xa.y, xb.y);
        uint64_t xp2 = pack2(xa.z, xb.z);
        uint64_t xp3 = pack2(xa.w, xb.w);
        uint64_t n0 = mul2(xp0, t[0][p][0]);
        n0 = fma2(xp1, t[1][p][0], n0);
        n0 = fma2(xp2, t[2][p][0], n0);
        n0 = fma2(xp3, t[3][p][0], n0);
        uint64_t n1 = mul2(xp0, t[0][p][1]);
        n1 = fma2(xp1, t[1][p][1], n1);
        n1 = fma2(xp2, t[2][p][1], n1);
        n1 = fma2(xp3, t[3][p][1], n1);
        ulonglong2 w; w.x = n0; w.y = n1;   // r = 2*lane, 2*lane+1
        scrW[p * 32 + lane] = w;
    }
}

__global__ void __launch_bounds__(THREADS, 1)
tt_chain_kernel(const float* __restrict__ x,    // [B, 128, 4]
                const float* __restrict__ fc,   // [4, 64]
                const float* __restrict__ mc,   // [126, 64, 4, 64]
                const float* __restrict__ lc,   // [64, 4]
                float* __restrict__ out)        // [B, 1]
{
    float*      Cbuf = smem_f;
    float2*     vbuf = (float2*)(smem_f + 2*CSTEP);       // [14][VPITCH]
    ulonglong2* scr  = (ulonglong2*)(vbuf + NPAIR*VPITCH); // [2][4][14][32]
    float2*     scrf = (float2*)scr;                       // f2 view [..][14][64]
    float2*     epi  = (float2*)scr;                       // aliases parity 0

    const int tid  = threadIdx.x;
    const int warp = tid >> 5;
    const int lane = tid & 31;
    const int q    = warp >> 2;            // l-quarter [16q, 16q+16)
    const int sg   = warp & 3;             // -> SMSP
    const int Pw   = (((q + sg) & 3) < 2) ? 4 : 3;
    int base = 0;
    #pragma unroll
    for (int t = 0; t < 3; ++t)
        if (t < sg) base += (((q + t) & 3) < 2) ? 4 : 3;

    // clamped x offsets for this warp's pairs
    int xo0[4], xo1[4];
    #pragma unroll
    for (int p = 0; p < 4; ++p) {
        int pb = base + p;
        int b0 = blockIdx.x * TB + 2 * pb;
        int b1 = b0 + 1;
        if (b0 > BATCH - 1) b0 = BATCH - 1;
        if (b1 > BATCH - 1) b1 = BATCH - 1;
        xo0[p] = b0 * (LEN * 4);
        xo1[p] = b1 * (LEN * 4);
    }

    // ---- prefetch C[0] ----
    {
        uint32_t dst = smem_u32(Cbuf);
        #pragma unroll
        for (int j = 0; j < 8; ++j) {
            int idx = j * THREADS + tid;
            cp_async16(dst + idx * 16, mc + idx * 4);
        }
        asm volatile("cp.async.commit_group;\n");
    }

    // ---- prologue: fill this warp's vbuf slots with v0 ----
    #pragma unroll
    for (int v = 0; v < 2; ++v) {
        int slot = lane + 32 * v;
        int pi = slot >> 4;
        int ro = slot & 15;
        if (pi < Pw) {
            int l = 16 * q + ro;
            float4 xA = *(const float4*)(x + xo0[pi]);
            float4 xB = *(const float4*)(x + xo1[pi]);
            float f0 = fc[l], f1 = fc[64 + l], f2 = fc[128 + l], f3 = fc[192 + l];
            float vx = f0*xA.x + f1*xA.y + f2*xA.z + f3*xA.w;
            float vy = f0*xB.x + f1*xB.y + f2*xB.z + f3*xB.w;
            vbuf[(base + pi) * VPITCH + l] = make_float2(vx, vy);
        }
    }
    asm volatile("cp.async.wait_group 0;\n");   // own C[0] chunks landed

    // ---- main chain: ONE __syncthreads per step ----
    #pragma unroll 1
    for (int s = 0; s < NSTEP; ++s) {
        __syncthreads();   // all C[s] copies landed; scr[(s-1)&1] complete; Cbuf[(s+1)&1] free

        if (s + 1 < NSTEP) {
            uint32_t dst = smem_u32(Cbuf + ((s + 1) & 1) * CSTEP);
            const float* src = mc + (size_t)(s + 1) * CSTEP;
            #pragma unroll
            for (int j = 0; j < 8; ++j) {
                int idx = j * THREADS + tid;
                cp_async16(dst + idx * 16, src + idx * 4);
            }
            asm volatile("cp.async.commit_group;\n");
        }

        // finalize v_s into vbuf (this warp's own slots), except s==0
        if (s > 0) {
            const int par = (s - 1) & 1;
            #pragma unroll
            for (int v = 0; v < 2; ++v) {
                int slot = lane + 32 * v;
                int pi = slot >> 4;
                int ro = slot & 15;
                if (pi < Pw) {
                    int pb = base + pi;
                    int l  = 16 * q + ro;
                    const float2* sp = scrf + (size_t)(par * 4) * (NPAIR * 64)
                                            + (size_t)pb * 64 + l;
                    float2 a = sp[0];
                    float2 b = sp[NPAIR * 64];
                    float2 c = sp[2 * NPAIR * 64];
                    float2 d = sp[3 * NPAIR * 64];
                    vbuf[pb * VPITCH + l] =
                        make_float2((a.x + b.x) + (c.x + d.x),
                                    (a.y + b.y) + (c.y + d.y));
                }
            }
        }
        __syncwarp();

        const float2* CsL = (const float2*)(Cbuf + (s & 1) * CSTEP)
                          + (size_t)(64 * q) * 32 + lane;
        const float2* vrow = vbuf + base * VPITCH + 16 * q;
        ulonglong2* scrW = scr + (size_t)(((s & 1) * 4 + q) * NPAIR + base) * 32;

        if (Pw == 4) step_body<4>(s, CsL, vrow, x, xo0, xo1, scrW, lane);
        else         step_body<3>(s, CsL, vrow, x, xo0, xo1, scrW, lane);

        asm volatile("cp.async.wait_group 0;\n");   // own C[s+1] chunks landed
    }

    // ---- epilogue: v_126 in scr parity 1; dot with last-site vector ----
    __syncthreads();
    {
        const int par = (NSTEP - 1) & 1;   // = 1
        #pragma unroll
        for (int v = 0; v < 2; ++v) {
            int slot = lane + 32 * v;
            int pi = slot >> 4;
            int ro = slot & 15;
            float2 contrib = make_float2(0.f, 0.f);
            int valid = (pi < Pw);
            int pb = base + (valid ? pi : 0);
            if (valid) {
                int l = 16 * q + ro;
                const float2* sp = scrf + (size_t)(par * 4) * (NPAIR * 64)
                                        + (size_t)pb * 64 + l;
                float2 a = sp[0];
                float2 b = sp[NPAIR * 64];
                float2 c = sp[2 * NPAIR * 64];
                float2 d = sp[3 * NPAIR * 64];
                float vx = (a.x + b.x) + (c.x + d.x);
                float vy = (a.y + b.y) + (c.y + d.y);
                float4 l4  = *(const float4*)(lc + l * 4);
                float4 xe0 = *(const float4*)(x + xo0[pi] + 127 * 4);
                float4 xe1 = *(const float4*)(x + xo1[pi] + 127 * 4);
                float lva = l4.x*xe0.x + l4.y*xe0.y + l4.z*xe0.z + l4.w*xe0.w;
                float lvb = l4.x*xe1.x + l4.y*xe1.y + l4.z*xe1.z + l4.w*xe1.w;
                contrib = make_float2(vx * lva, vy * lvb);
            }
            // reduce over ro within each 16-lane group
            #pragma unroll
            for (int off = 8; off > 0; off >>= 1) {
                contrib.x += __shfl_down_sync(0xffffffffu, contrib.x, off, 16);
                contrib.y += __shfl_down_sync(0xffffffffu, contrib.y, off, 16);
            }
            __syncwarp();                      // scr reads done before epi alias write
            if (ro == 0 && valid)
                epi[q * NPAIR + pb] = contrib; // parity-0 region, disjoint from par1
        }
    }
    __syncthreads();
    if (tid < TB) {
        int b = blockIdx.x * TB + tid;
        if (b < BATCH) {
            int pb = tid >> 1;
            float sum = 0.f;
            #pragma unroll
            for (int qq = 0; qq < 4; ++qq) {
                float2 e = epi[qq * NPAIR + pb];
                sum += (tid & 1) ? e.y : e.x;
            }
            out[b] = sum;
        }
    }
}

extern "C" void kernel_launch(void* const* d_in, const int* in_sizes, int n_in,
                              void* d_out, int out_size) {
    const float* x  = (const float*)d_in[0];   // input_data [4096,128,4]
    const float* fc = (const float*)d_in[1];   // first_core [4,64]
    const float* mc = (const float*)d_in[2];   // mid_cores  [126,64,4,64]
    const float* lc = (const float*)d_in[3];   // last_core  [64,4]
    float* out = (float*)d_out;

    cudaFuncSetAttribute(tt_chain_kernel,
                         cudaFuncAttributeMaxDynamicSharedMemorySize, SMEM_BYTES);

    tt_chain_kernel<<<GRID, THREADS, SMEM_BYTES>>>(x, fc, mc, lc, out);
}